// round 1
// baseline (speedup 1.0000x reference)
#include <cuda_runtime.h>
#include <math.h>
#include <stdint.h>

// Problem constants (fixed by the reference)
#define Bq   8
#define Nn   20000
#define Ee   320000
#define Ccells 128
#define Dd   64
#define HOPS 4
#define HID  512
#define OUTD 256
#define K1   (HOPS*Dd)      // 256
#define ROWS (Bq*Nn)        // 160000
#define BND  ((size_t)Bq*Nn*Dd)

// ---------------- device scratch (static, no allocation) ----------------
__device__ int   g_idx[Nn];
__device__ float g_init[Nn*Dd];
__device__ float g_hops[HOPS][(size_t)Bq*Nn*Dd];   // hop outputs 1..4
__device__ float g_x[(size_t)ROWS*HID];            // GEMM1 output, LN in-place
__device__ int   g_deg[ROWS];
__device__ int   g_cursor[ROWS];
__device__ int   g_rowptr[Bq*(Nn+1)];
__device__ int   g_cols[(size_t)Bq*Ee];

// ---------------- argmax over cells -> gene index ----------------
__global__ void k_argmax(const float* __restrict__ poh) {
    int n = blockIdx.x * blockDim.x + threadIdx.x;
    if (n >= Nn) return;
    float best = poh[n]; int bi = 0;
    for (int c = 1; c < Ccells; c++) {
        float v = poh[(size_t)c * Nn + n];
        if (v > best) { best = v; bi = c; }
    }
    g_idx[n] = bi;
}

__global__ void k_init_emb(const float* __restrict__ emb) {
    int i = blockIdx.x * blockDim.x + threadIdx.x;
    if (i >= Nn * Dd) return;
    int n = i >> 6, d = i & 63;
    g_init[i] = emb[g_idx[n] * Dd + d];
}

// ---------------- CSR build ----------------
__global__ void k_zero_deg() {
    for (int i = blockIdx.x * blockDim.x + threadIdx.x; i < ROWS;
         i += gridDim.x * blockDim.x)
        g_deg[i] = 0;
}

__global__ void k_count(const int* __restrict__ edge) {
    int e = blockIdx.x * blockDim.x + threadIdx.x;
    if (e >= Bq * Ee) return;
    int b = e / Ee, i = e - b * Ee;
    int row = edge[(size_t)b * 2 * Ee + i];
    atomicAdd(&g_deg[b * Nn + row], 1);
}

// one block per graph: chunked exclusive scan of degrees
__global__ void k_scan() {
    __shared__ int part[640];
    int b = blockIdx.x;
    int t = threadIdx.x;          // 640 threads, 32 rows each
    int base = b * Nn;
    int s = 0;
    for (int i = 0; i < 32; i++) {
        int r = t * 32 + i;
        if (r < Nn) s += g_deg[base + r];
    }
    part[t] = s;
    __syncthreads();
    if (t == 0) {
        int run = 0;
        for (int i = 0; i < 640; i++) { int x = part[i]; part[i] = run; run += x; }
        g_rowptr[b * (Nn + 1) + Nn] = run;
    }
    __syncthreads();
    int off = part[t];
    for (int i = 0; i < 32; i++) {
        int r = t * 32 + i;
        if (r < Nn) {
            g_rowptr[b * (Nn + 1) + r] = off;
            g_cursor[base + r] = off;
            off += g_deg[base + r];
        }
    }
}

__global__ void k_scatter(const int* __restrict__ edge) {
    int e = blockIdx.x * blockDim.x + threadIdx.x;
    if (e >= Bq * Ee) return;
    int b = e / Ee, i = e - b * Ee;
    int row = edge[(size_t)b * 2 * Ee + i];
    int col = edge[(size_t)b * 2 * Ee + Ee + i];
    int pos = atomicAdd(&g_cursor[b * Nn + row], 1);
    g_cols[(size_t)b * Ee + pos] = col;
}

// ---------------- SPMM gather: one warp per output row ----------------
__global__ void k_spmm(int hop) {
    int w = blockIdx.x * (blockDim.x >> 5) + (threadIdx.x >> 5);
    if (w >= ROWS) return;
    int lane = threadIdx.x & 31;
    int b = w / Nn, n = w - b * Nn;
    int s = g_rowptr[b * (Nn + 1) + n];
    int e = g_rowptr[b * (Nn + 1) + n + 1];
    const float2* __restrict__ src =
        (hop == 0) ? (const float2*)g_init : (const float2*)g_hops[hop - 1];
    size_t grow = (hop == 0) ? 0 : (size_t)b * Nn;
    float2 acc = make_float2(0.f, 0.f);
    const int* __restrict__ cols = &g_cols[(size_t)b * Ee];
    for (int j = s; j < e; j++) {
        int c = cols[j];
        float2 v = src[(grow + (size_t)c) * 32 + lane];
        acc.x += v.x; acc.y += v.y;
    }
    ((float2*)g_hops[hop])[(size_t)w * 32 + lane] = acc;
}

// ---------------- tiled fp32 GEMM (64x64x16, 4x4 microtile) ----------------
// GATHER=1: A[m][k] gathered from g_hops (k = 4d+h), C -> g_x, bias=b1
// GATHER=0: A = g_x, C -> param (d_out), bias=b2
template <int KDIM, int NDIM, int GATHER>
__global__ void k_gemm(const float* __restrict__ Bm,
                       const float* __restrict__ bias,
                       float* __restrict__ CmParam) {
    __shared__ float As[16][64];
    __shared__ float Bs[16][64];
    int tid = threadIdx.x;            // 256 threads
    int m0 = blockIdx.x * 64;
    int n0 = blockIdx.y * 64;
    int tx = tid & 15, ty = tid >> 4;
    int ml = tid >> 2;                // 0..63
    int kb = (tid & 3) * 4;           // 0,4,8,12

    float acc[4][4] = {};

    for (int k0 = 0; k0 < KDIM; k0 += 16) {
        // A tile
        if (GATHER) {
            int d = (k0 >> 2) + (tid & 3);
            size_t off = (size_t)(m0 + ml) * Dd + d;
            #pragma unroll
            for (int j = 0; j < 4; j++)
                As[kb + j][ml] = g_hops[j][off];
        } else {
            const float4 v = *(const float4*)&g_x[(size_t)(m0 + ml) * KDIM + k0 + kb];
            As[kb + 0][ml] = v.x; As[kb + 1][ml] = v.y;
            As[kb + 2][ml] = v.z; As[kb + 3][ml] = v.w;
        }
        // B tile
        {
            int kr = tid >> 4;        // 0..15
            int nc = (tid & 15) * 4;
            *(float4*)&Bs[kr][nc] =
                *(const float4*)&Bm[(size_t)(k0 + kr) * NDIM + n0 + nc];
        }
        __syncthreads();
        #pragma unroll
        for (int kk = 0; kk < 16; kk++) {
            float4 a = *(const float4*)&As[kk][ty * 4];
            float4 bv = *(const float4*)&Bs[kk][tx * 4];
            float av[4] = {a.x, a.y, a.z, a.w};
            float bb[4] = {bv.x, bv.y, bv.z, bv.w};
            #pragma unroll
            for (int i = 0; i < 4; i++)
                #pragma unroll
                for (int j = 0; j < 4; j++)
                    acc[i][j] += av[i] * bb[j];
        }
        __syncthreads();
    }

    float* Cm = GATHER ? g_x : CmParam;
    #pragma unroll
    for (int i = 0; i < 4; i++) {
        size_t m = m0 + ty * 4 + i;
        #pragma unroll
        for (int j = 0; j < 4; j++) {
            int n = n0 + tx * 4 + j;
            Cm[m * NDIM + n] = acc[i][j] + bias[n];
        }
    }
}

// ---------------- LayerNorm + exact GELU, in-place on g_x ----------------
__global__ void k_lngelu(const float* __restrict__ gamma,
                         const float* __restrict__ beta) {
    int w = blockIdx.x * (blockDim.x >> 5) + (threadIdx.x >> 5);
    if (w >= ROWS) return;
    int lane = threadIdx.x & 31;
    float* row = g_x + (size_t)w * HID;
    float4 v[4];
    float s = 0.f, ss = 0.f;
    #pragma unroll
    for (int p = 0; p < 4; p++) {
        v[p] = *(float4*)&row[p * 128 + lane * 4];
        s  += v[p].x + v[p].y + v[p].z + v[p].w;
        ss += v[p].x * v[p].x + v[p].y * v[p].y + v[p].z * v[p].z + v[p].w * v[p].w;
    }
    #pragma unroll
    for (int o = 16; o; o >>= 1) {
        s  += __shfl_xor_sync(0xffffffffu, s, o);
        ss += __shfl_xor_sync(0xffffffffu, ss, o);
    }
    float mu = s * (1.f / HID);
    float var = ss * (1.f / HID) - mu * mu;
    float r = rsqrtf(var + 1e-5f);
    #pragma unroll
    for (int p = 0; p < 4; p++) {
        int k0 = p * 128 + lane * 4;
        float vals[4] = {v[p].x, v[p].y, v[p].z, v[p].w};
        #pragma unroll
        for (int j = 0; j < 4; j++) {
            float t = (vals[j] - mu) * r * gamma[k0 + j] + beta[k0 + j];
            vals[j] = t * normcdff(t);   // exact gelu: x * Phi(x)
        }
        *(float4*)&row[k0] = make_float4(vals[0], vals[1], vals[2], vals[3]);
    }
}

// ---------------- launch ----------------
extern "C" void kernel_launch(void* const* d_in, const int* in_sizes, int n_in,
                              void* d_out, int out_size) {
    // Resolve inputs in order, skipping any scalar (num_nodes) entries.
    int p = 0;
    auto pick = [&]() -> const void* {
        while (p < n_in && in_sizes[p] <= 1) p++;
        return d_in[p++];
    };
    const int*   edge  = (const int*)  pick();  // (B,2,E) int32
    const float* poh   = (const float*)pick();  // (C,N)
    const float* emb   = (const float*)pick();  // (C,D)
    const float* W1    = (const float*)pick();  // (256,512)
    const float* b1    = (const float*)pick();  // (512,)
    const float* gamma = (const float*)pick();  // (512,)
    const float* beta  = (const float*)pick();  // (512,)
    const float* W2    = (const float*)pick();  // (512,256)
    const float* b2    = (const float*)pick();  // (256,)
    float* out = (float*)d_out;                 // (B,N,256)

    // init embedding
    k_argmax<<<(Nn + 255) / 256, 256>>>(poh);
    k_init_emb<<<(Nn * Dd + 255) / 256, 256>>>(emb);

    // CSR build (per graph)
    k_zero_deg<<<256, 256>>>();
    k_count<<<(Bq * Ee + 255) / 256, 256>>>(edge);
    k_scan<<<Bq, 640>>>();
    k_scatter<<<(Bq * Ee + 255) / 256, 256>>>(edge);

    // 4 hops of SPMM (warp per row)
    for (int h = 0; h < HOPS; h++)
        k_spmm<<<ROWS / 8, 256>>>(h);

    // x = omega @ W1 + b1   (A gathered from hop buffers)
    {
        dim3 grid(ROWS / 64, HID / 64);
        k_gemm<K1, HID, 1><<<grid, 256>>>(W1, b1, nullptr);
    }

    // LayerNorm + GELU in place
    k_lngelu<<<ROWS / 8, 256>>>(gamma, beta);

    // out = y @ W2 + b2
    {
        dim3 grid(ROWS / 64, OUTD / 64);
        k_gemm<HID, OUTD, 0><<<grid, 256>>>(W2, b2, out);
    }
}

// round 2
// speedup vs baseline: 1.9419x; 1.9419x over previous
#include <cuda_runtime.h>
#include <math.h>
#include <stdint.h>

#define Bq   8
#define Nn   20000
#define Ee   320000
#define Ccells 128
#define Dd   64
#define HOPS 4
#define HID  512
#define OUTD 256
#define K1   (HOPS*Dd)      // 256
#define ROWS (Bq*Nn)        // 160000

// ---------------- device scratch (static, no allocation) ----------------
__device__ int   g_idx[Nn];
__device__ float g_init[Nn*Dd];
__device__ float g_hops[HOPS][(size_t)Bq*Nn*Dd];
__device__ float g_x[(size_t)ROWS*HID];
__device__ int   g_deg[ROWS];
__device__ int   g_cursor[ROWS];
__device__ int   g_rowptr[Bq*(Nn+1)];
__device__ int   g_cols[(size_t)Bq*Ee];

// ---------------- helpers ----------------
__device__ __forceinline__ float f2tf32(float x) {
    uint32_t u;
    asm("cvt.rna.tf32.f32 %0, %1;" : "=r"(u) : "f"(x));
    return __uint_as_float(u);
}

__device__ __forceinline__ void mma_tf32(float c[4],
    uint32_t a0, uint32_t a1, uint32_t a2, uint32_t a3,
    uint32_t b0, uint32_t b1) {
    asm volatile(
        "mma.sync.aligned.m16n8k8.row.col.f32.tf32.tf32.f32 "
        "{%0,%1,%2,%3}, {%4,%5,%6,%7}, {%8,%9}, {%0,%1,%2,%3};\n"
        : "+f"(c[0]), "+f"(c[1]), "+f"(c[2]), "+f"(c[3])
        : "r"(a0), "r"(a1), "r"(a2), "r"(a3), "r"(b0), "r"(b1));
}

// ---------------- argmax over cells -> gene index ----------------
__global__ void k_argmax(const float* __restrict__ poh) {
    int n = blockIdx.x * blockDim.x + threadIdx.x;
    if (n >= Nn) return;
    float best = poh[n]; int bi = 0;
    for (int c = 1; c < Ccells; c++) {
        float v = poh[(size_t)c * Nn + n];
        if (v > best) { best = v; bi = c; }
    }
    g_idx[n] = bi;
}

__global__ void k_init_emb(const float* __restrict__ emb) {
    int i = blockIdx.x * blockDim.x + threadIdx.x;
    if (i >= Nn * Dd) return;
    int n = i >> 6, d = i & 63;
    g_init[i] = emb[g_idx[n] * Dd + d];
}

// ---------------- CSR build ----------------
__global__ void k_zero_deg() {
    for (int i = blockIdx.x * blockDim.x + threadIdx.x; i < ROWS;
         i += gridDim.x * blockDim.x)
        g_deg[i] = 0;
}

__global__ void k_count(const int* __restrict__ edge) {
    int e = blockIdx.x * blockDim.x + threadIdx.x;
    if (e >= Bq * Ee) return;
    int b = e / Ee, i = e - b * Ee;
    int row = edge[(size_t)b * 2 * Ee + i];
    atomicAdd(&g_deg[b * Nn + row], 1);
}

__global__ void k_scan() {
    __shared__ int part[640];
    int b = blockIdx.x;
    int t = threadIdx.x;
    int base = b * Nn;
    int s = 0;
    for (int i = 0; i < 32; i++) {
        int r = t * 32 + i;
        if (r < Nn) s += g_deg[base + r];
    }
    part[t] = s;
    __syncthreads();
    if (t == 0) {
        int run = 0;
        for (int i = 0; i < 640; i++) { int x = part[i]; part[i] = run; run += x; }
        g_rowptr[b * (Nn + 1) + Nn] = run;
    }
    __syncthreads();
    int off = part[t];
    for (int i = 0; i < 32; i++) {
        int r = t * 32 + i;
        if (r < Nn) {
            g_rowptr[b * (Nn + 1) + r] = off;
            g_cursor[base + r] = off;
            off += g_deg[base + r];
        }
    }
}

__global__ void k_scatter(const int* __restrict__ edge) {
    int e = blockIdx.x * blockDim.x + threadIdx.x;
    if (e >= Bq * Ee) return;
    int b = e / Ee, i = e - b * Ee;
    int row = edge[(size_t)b * 2 * Ee + i];
    int col = edge[(size_t)b * 2 * Ee + Ee + i];
    int pos = atomicAdd(&g_cursor[b * Nn + row], 1);
    g_cols[(size_t)b * Ee + pos] = col;
}

// ---------------- SPMM gather: one warp per output row, 2-way MLP ----------------
__global__ void k_spmm(int hop) {
    int w = blockIdx.x * (blockDim.x >> 5) + (threadIdx.x >> 5);
    if (w >= ROWS) return;
    int lane = threadIdx.x & 31;
    int b = w / Nn, n = w - b * Nn;
    int s = g_rowptr[b * (Nn + 1) + n];
    int e = g_rowptr[b * (Nn + 1) + n + 1];
    const float2* __restrict__ src =
        (hop == 0) ? (const float2*)g_init : (const float2*)g_hops[hop - 1];
    size_t grow = (hop == 0) ? 0 : (size_t)b * Nn;
    float2 acc0 = make_float2(0.f, 0.f);
    float2 acc1 = make_float2(0.f, 0.f);
    const int* __restrict__ cols = &g_cols[(size_t)b * Ee];
    int j = s;
    for (; j + 1 < e; j += 2) {
        int c0 = cols[j], c1 = cols[j + 1];
        float2 v0 = src[(grow + (size_t)c0) * 32 + lane];
        float2 v1 = src[(grow + (size_t)c1) * 32 + lane];
        acc0.x += v0.x; acc0.y += v0.y;
        acc1.x += v1.x; acc1.y += v1.y;
    }
    if (j < e) {
        float2 v = src[(grow + (size_t)cols[j]) * 32 + lane];
        acc0.x += v.x; acc0.y += v.y;
    }
    acc0.x += acc1.x; acc0.y += acc1.y;
    ((float2*)g_hops[hop])[(size_t)w * 32 + lane] = acc0;
}

// ---------------- TF32 tensor-core GEMM: CTA 128x128, K-step 32 ----------------
// GATHER=1: A gathered from g_hops (k = 4d+h), C -> g_x, bias=b1
// GATHER=0: A = g_x, C -> Cparam, bias=b2
template <int KDIM, int NDIM, int GATHER>
__global__ void __launch_bounds__(256, 2)
k_gemm_tc(const float* __restrict__ Bm,
          const float* __restrict__ bias,
          float* __restrict__ Cparam) {
    __shared__ float As[128][36];    // [m][k], padded
    __shared__ float Bs[32][132];    // [k][n], padded

    const int tid  = threadIdx.x;
    const int lane = tid & 31;
    const int warp = tid >> 5;
    const int g    = lane >> 2;      // 0..7
    const int tg   = lane & 3;       // 0..3
    const int wm   = warp & 3;       // 4 m-warps
    const int wn   = warp >> 2;      // 2 n-warps
    const int m0w  = wm * 32;
    const int n0w  = wn * 64;

    const int m0 = blockIdx.x * 128;
    const int n0 = blockIdx.y * 128;

    float acc[2][8][4];
    #pragma unroll
    for (int i = 0; i < 2; i++)
        #pragma unroll
        for (int j = 0; j < 8; j++)
            #pragma unroll
            for (int q = 0; q < 4; q++) acc[i][j][q] = 0.f;

    // per-thread load coordinates
    const int am   = tid >> 1;           // 0..127
    const int ahalf = tid & 1;           // k half (16 each)
    const int bk   = tid >> 3;           // 0..31
    const int bnq  = (tid & 7) * 16;     // 16 n per thread

    for (int k0 = 0; k0 < KDIM; k0 += 32) {
        // ---- stage A tile ----
        if (GATHER) {
            int dbase = (k0 >> 2) + ahalf * 4;
            size_t rowoff = (size_t)(m0 + am) * Dd + dbase;
            #pragma unroll
            for (int h = 0; h < 4; h++) {
                float4 v = *(const float4*)&g_hops[h][rowoff];
                As[am][ahalf * 16 + 0 + h]  = f2tf32(v.x);
                As[am][ahalf * 16 + 4 + h]  = f2tf32(v.y);
                As[am][ahalf * 16 + 8 + h]  = f2tf32(v.z);
                As[am][ahalf * 16 + 12 + h] = f2tf32(v.w);
            }
        } else {
            const float* srcA = &g_x[(size_t)(m0 + am) * KDIM + k0 + ahalf * 16];
            #pragma unroll
            for (int i = 0; i < 4; i++) {
                float4 v = *(const float4*)(srcA + i * 4);
                float4 c = make_float4(f2tf32(v.x), f2tf32(v.y), f2tf32(v.z), f2tf32(v.w));
                *(float4*)&As[am][ahalf * 16 + i * 4] = c;
            }
        }
        // ---- stage B tile ----
        {
            const float* srcB = &Bm[(size_t)(k0 + bk) * NDIM + n0 + bnq];
            #pragma unroll
            for (int i = 0; i < 4; i++) {
                float4 v = *(const float4*)(srcB + i * 4);
                float4 c = make_float4(f2tf32(v.x), f2tf32(v.y), f2tf32(v.z), f2tf32(v.w));
                *(float4*)&Bs[bk][bnq + i * 4] = c;
            }
        }
        __syncthreads();

        // ---- compute: 4 k8 sub-steps ----
        #pragma unroll
        for (int kk = 0; kk < 32; kk += 8) {
            uint32_t afr[2][4];
            #pragma unroll
            for (int mi = 0; mi < 2; mi++) {
                int mr = m0w + mi * 16 + g;
                afr[mi][0] = __float_as_uint(As[mr][kk + tg]);
                afr[mi][1] = __float_as_uint(As[mr + 8][kk + tg]);
                afr[mi][2] = __float_as_uint(As[mr][kk + tg + 4]);
                afr[mi][3] = __float_as_uint(As[mr + 8][kk + tg + 4]);
            }
            uint32_t bfr[8][2];
            #pragma unroll
            for (int nf = 0; nf < 8; nf++) {
                int nc = n0w + nf * 8 + g;
                bfr[nf][0] = __float_as_uint(Bs[kk + tg][nc]);
                bfr[nf][1] = __float_as_uint(Bs[kk + tg + 4][nc]);
            }
            #pragma unroll
            for (int mi = 0; mi < 2; mi++)
                #pragma unroll
                for (int nf = 0; nf < 8; nf++)
                    mma_tf32(acc[mi][nf],
                             afr[mi][0], afr[mi][1], afr[mi][2], afr[mi][3],
                             bfr[nf][0], bfr[nf][1]);
        }
        __syncthreads();
    }

    // ---- epilogue: bias + store ----
    float* Cm = GATHER ? g_x : Cparam;
    #pragma unroll
    for (int mi = 0; mi < 2; mi++) {
        #pragma unroll
        for (int nf = 0; nf < 8; nf++) {
            int n = n0 + n0w + nf * 8 + 2 * tg;
            float bv0 = bias[n], bv1 = bias[n + 1];
            size_t mA = (size_t)(m0 + m0w + mi * 16 + g);
            size_t mB = mA + 8;
            float2 r0 = make_float2(acc[mi][nf][0] + bv0, acc[mi][nf][1] + bv1);
            float2 r1 = make_float2(acc[mi][nf][2] + bv0, acc[mi][nf][3] + bv1);
            *(float2*)&Cm[mA * NDIM + n] = r0;
            *(float2*)&Cm[mB * NDIM + n] = r1;
        }
    }
}

// ---------------- LayerNorm + exact GELU, in-place on g_x ----------------
__global__ void k_lngelu(const float* __restrict__ gamma,
                         const float* __restrict__ beta) {
    int w = blockIdx.x * (blockDim.x >> 5) + (threadIdx.x >> 5);
    if (w >= ROWS) return;
    int lane = threadIdx.x & 31;
    float* row = g_x + (size_t)w * HID;
    float4 v[4];
    float s = 0.f, ss = 0.f;
    #pragma unroll
    for (int p = 0; p < 4; p++) {
        v[p] = *(float4*)&row[p * 128 + lane * 4];
        s  += v[p].x + v[p].y + v[p].z + v[p].w;
        ss += v[p].x * v[p].x + v[p].y * v[p].y + v[p].z * v[p].z + v[p].w * v[p].w;
    }
    #pragma unroll
    for (int o = 16; o; o >>= 1) {
        s  += __shfl_xor_sync(0xffffffffu, s, o);
        ss += __shfl_xor_sync(0xffffffffu, ss, o);
    }
    float mu = s * (1.f / HID);
    float var = ss * (1.f / HID) - mu * mu;
    float r = rsqrtf(var + 1e-5f);
    #pragma unroll
    for (int p = 0; p < 4; p++) {
        int k0 = p * 128 + lane * 4;
        float vals[4] = {v[p].x, v[p].y, v[p].z, v[p].w};
        #pragma unroll
        for (int j = 0; j < 4; j++) {
            float t = (vals[j] - mu) * r * gamma[k0 + j] + beta[k0 + j];
            vals[j] = t * normcdff(t);
        }
        *(float4*)&row[k0] = make_float4(vals[0], vals[1], vals[2], vals[3]);
    }
}

// ---------------- launch ----------------
extern "C" void kernel_launch(void* const* d_in, const int* in_sizes, int n_in,
                              void* d_out, int out_size) {
    int p = 0;
    auto pick = [&]() -> const void* {
        while (p < n_in && in_sizes[p] <= 1) p++;
        return d_in[p++];
    };
    const int*   edge  = (const int*)  pick();
    const float* poh   = (const float*)pick();
    const float* emb   = (const float*)pick();
    const float* W1    = (const float*)pick();
    const float* b1    = (const float*)pick();
    const float* gamma = (const float*)pick();
    const float* beta  = (const float*)pick();
    const float* W2    = (const float*)pick();
    const float* b2    = (const float*)pick();
    float* out = (float*)d_out;

    k_argmax<<<(Nn + 255) / 256, 256>>>(poh);
    k_init_emb<<<(Nn * Dd + 255) / 256, 256>>>(emb);

    k_zero_deg<<<256, 256>>>();
    k_count<<<(Bq * Ee + 255) / 256, 256>>>(edge);
    k_scan<<<Bq, 640>>>();
    k_scatter<<<(Bq * Ee + 255) / 256, 256>>>(edge);

    for (int h = 0; h < HOPS; h++)
        k_spmm<<<ROWS / 8, 256>>>(h);

    {
        dim3 grid(ROWS / 128, HID / 128);
        k_gemm_tc<K1, HID, 1><<<grid, 256>>>(W1, b1, nullptr);
    }

    k_lngelu<<<ROWS / 8, 256>>>(gamma, beta);

    {
        dim3 grid(ROWS / 128, OUTD / 128);
        k_gemm_tc<HID, OUTD, 0><<<grid, 256>>>(W2, b2, out);
    }
}

// round 4
// speedup vs baseline: 2.1200x; 1.0917x over previous
#include <cuda_runtime.h>
#include <math.h>
#include <stdint.h>

#define Bq   8
#define Nn   20000
#define Ee   320000
#define Ccells 128
#define Dd   64
#define HOPS 4
#define HID  512
#define OUTD 256
#define K1   (HOPS*Dd)      // 256
#define ROWS (Bq*Nn)        // 160000

// ---------------- device scratch (static, no allocation) ----------------
__device__ int   g_idx[Nn];
__device__ float g_init[Nn*Dd];
__device__ float g_hops[HOPS][(size_t)Bq*Nn*Dd];
__device__ float g_x[(size_t)ROWS*HID];
__device__ int   g_deg[ROWS];
__device__ int   g_cursor[ROWS];
__device__ int   g_rowptr[Bq*(Nn+1)];
__device__ int   g_cols[(size_t)Bq*Ee];
__device__ float g_W1r[(size_t)K1*HID];    // [k_blocked][n], tf32-rounded, rows permuted
__device__ float g_W2r[(size_t)HID*OUTD];  // [k][n], tf32-rounded

// ---------------- helpers ----------------
__device__ __forceinline__ float f2tf32(float x) {
    uint32_t u;
    asm("cvt.rna.tf32.f32 %0, %1;" : "=r"(u) : "f"(x));
    return __uint_as_float(u);
}

__device__ __forceinline__ void mma_tf32(float c[4],
    uint32_t a0, uint32_t a1, uint32_t a2, uint32_t a3,
    uint32_t b0, uint32_t b1) {
    asm volatile(
        "mma.sync.aligned.m16n8k8.row.col.f32.tf32.tf32.f32 "
        "{%0,%1,%2,%3}, {%4,%5,%6,%7}, {%8,%9}, {%0,%1,%2,%3};\n"
        : "+f"(c[0]), "+f"(c[1]), "+f"(c[2]), "+f"(c[3])
        : "r"(a0), "r"(a1), "r"(a2), "r"(a3), "r"(b0), "r"(b1));
}

// ---------------- argmax over cells -> gene index ----------------
__global__ void k_argmax(const float* __restrict__ poh) {
    int n = blockIdx.x * blockDim.x + threadIdx.x;
    if (n >= Nn) return;
    float best = poh[n]; int bi = 0;
    for (int c = 1; c < Ccells; c++) {
        float v = poh[(size_t)c * Nn + n];
        if (v > best) { best = v; bi = c; }
    }
    g_idx[n] = bi;
}

__global__ void k_init_emb(const float* __restrict__ emb) {
    int i = blockIdx.x * blockDim.x + threadIdx.x;
    if (i >= Nn * Dd) return;
    int n = i >> 6, d = i & 63;
    g_init[i] = emb[g_idx[n] * Dd + d];
}

// ---------------- weight prep ----------------
// W1 (K1=256 rows interleaved k=d*4+h, HID cols) -> blocked rows kb=h*64+d, tf32
__global__ void k_prepW1(const float* __restrict__ W1) {
    int i = blockIdx.x * blockDim.x + threadIdx.x;
    if (i >= K1 * HID) return;
    int k = i / HID, n = i - k * HID;
    int d = k >> 2, h = k & 3;
    g_W1r[(size_t)(h * 64 + d) * HID + n] = f2tf32(W1[i]);
}
__global__ void k_prepW2(const float* __restrict__ W2) {
    int i = blockIdx.x * blockDim.x + threadIdx.x;
    if (i >= HID * OUTD) return;
    g_W2r[i] = f2tf32(W2[i]);
}

// ---------------- CSR build ----------------
__global__ void k_zero_deg() {
    for (int i = blockIdx.x * blockDim.x + threadIdx.x; i < ROWS;
         i += gridDim.x * blockDim.x)
        g_deg[i] = 0;
}

__global__ void k_count(const int* __restrict__ edge) {
    int e = blockIdx.x * blockDim.x + threadIdx.x;
    if (e >= Bq * Ee) return;
    int b = e / Ee, i = e - b * Ee;
    int row = edge[(size_t)b * 2 * Ee + i];
    atomicAdd(&g_deg[b * Nn + row], 1);
}

__global__ void k_scan() {
    __shared__ int part[640];
    int b = blockIdx.x;
    int t = threadIdx.x;
    int base = b * Nn;
    int s = 0;
    for (int i = 0; i < 32; i++) {
        int r = t * 32 + i;
        if (r < Nn) s += g_deg[base + r];
    }
    part[t] = s;
    __syncthreads();
    if (t == 0) {
        int run = 0;
        for (int i = 0; i < 640; i++) { int x = part[i]; part[i] = run; run += x; }
        g_rowptr[b * (Nn + 1) + Nn] = run;
    }
    __syncthreads();
    int off = part[t];
    for (int i = 0; i < 32; i++) {
        int r = t * 32 + i;
        if (r < Nn) {
            g_rowptr[b * (Nn + 1) + r] = off;
            g_cursor[base + r] = off;
            off += g_deg[base + r];
        }
    }
}

__global__ void k_scatter(const int* __restrict__ edge) {
    int e = blockIdx.x * blockDim.x + threadIdx.x;
    if (e >= Bq * Ee) return;
    int b = e / Ee, i = e - b * Ee;
    int row = edge[(size_t)b * 2 * Ee + i];
    int col = edge[(size_t)b * 2 * Ee + Ee + i];
    int pos = atomicAdd(&g_cursor[b * Nn + row], 1);
    g_cols[(size_t)b * Ee + pos] = col;
}

// ---------------- SPMM gather: one warp per output row, 4-way MLP ----------------
__global__ void k_spmm(int hop) {
    int w = blockIdx.x * (blockDim.x >> 5) + (threadIdx.x >> 5);
    if (w >= ROWS) return;
    int lane = threadIdx.x & 31;
    int b = w / Nn, n = w - b * Nn;
    int s = g_rowptr[b * (Nn + 1) + n];
    int e = g_rowptr[b * (Nn + 1) + n + 1];
    const float2* __restrict__ src =
        (hop == 0) ? (const float2*)g_init : (const float2*)g_hops[hop - 1];
    size_t grow = (hop == 0) ? 0 : (size_t)b * Nn;
    float2 a0 = make_float2(0.f, 0.f), a1 = a0, a2 = a0, a3 = a0;
    const int* __restrict__ cols = &g_cols[(size_t)b * Ee];
    int j = s;
    for (; j + 3 < e; j += 4) {
        int c0 = cols[j], c1 = cols[j + 1], c2 = cols[j + 2], c3 = cols[j + 3];
        float2 v0 = src[(grow + (size_t)c0) * 32 + lane];
        float2 v1 = src[(grow + (size_t)c1) * 32 + lane];
        float2 v2 = src[(grow + (size_t)c2) * 32 + lane];
        float2 v3 = src[(grow + (size_t)c3) * 32 + lane];
        a0.x += v0.x; a0.y += v0.y;
        a1.x += v1.x; a1.y += v1.y;
        a2.x += v2.x; a2.y += v2.y;
        a3.x += v3.x; a3.y += v3.y;
    }
    for (; j < e; j++) {
        float2 v = src[(grow + (size_t)cols[j]) * 32 + lane];
        a0.x += v.x; a0.y += v.y;
    }
    a0.x += a1.x + a2.x + a3.x;
    a0.y += a1.y + a2.y + a3.y;
    ((float2*)g_hops[hop])[(size_t)w * 32 + lane] = a0;
}

// ---------------- TF32 tensor-core GEMM: 128x128 CTA, K-step 32 ----------------
// Software-pipelined: regs stage tile kt+1 while computing kt; double smem buffers.
// GATHER=1: A from g_hops (blocked k = h*64+d), C -> g_x, bias=b1, cvt at stage.
// GATHER=0: A = g_x (pre-rounded tf32 by LN), C -> Cparam, bias=b2.
// Grid: (NDIM/128, ROWS/128) -- n fastest for L2 reuse of A across n-tiles.
#define AS_FLOATS (128*36)
#define BS_FLOATS (32*132)
#define GEMM_SMEM_BYTES ((2*AS_FLOATS + 2*BS_FLOATS)*4)

template <int KDIM, int NDIM, int GATHER>
__global__ void __launch_bounds__(256)
k_gemm_tc(const float* __restrict__ Wr,
          const float* __restrict__ bias,
          float* __restrict__ Cparam) {
    extern __shared__ float sm[];
    float* Asb = sm;                    // 2 buffers of [128][36]
    float* Bsb = sm + 2 * AS_FLOATS;    // 2 buffers of [32][132]

    const int tid  = threadIdx.x;
    const int lane = tid & 31;
    const int warp = tid >> 5;
    const int g    = lane >> 2;
    const int tg   = lane & 3;
    const int wm   = warp & 3;
    const int wn   = warp >> 2;
    const int m0w  = wm * 32;
    const int n0w  = wn * 64;

    const int n0 = blockIdx.x * 128;
    const int m0 = blockIdx.y * 128;

    float acc[2][8][4];
    #pragma unroll
    for (int i = 0; i < 2; i++)
        #pragma unroll
        for (int j = 0; j < 8; j++)
            #pragma unroll
            for (int q = 0; q < 4; q++) acc[i][j][q] = 0.f;

    const int am = tid >> 1;         // A row 0..127
    const int ah = tid & 1;          // k half
    const int bk = tid >> 3;         // B k row 0..31
    const int bq = (tid & 7) * 16;   // B n offset

    float4 ar[4], br[4];

    auto ldA = [&](int kt) {
        const int k0 = kt * 32;
        const float* src;
        if (GATHER) {
            int h  = k0 >> 6;
            int d0 = (k0 & 63) + ah * 16;
            src = &g_hops[h][(size_t)(m0 + am) * Dd + d0];
        } else {
            src = &g_x[(size_t)(m0 + am) * KDIM + k0 + ah * 16];
        }
        #pragma unroll
        for (int i = 0; i < 4; i++) ar[i] = *(const float4*)(src + i * 4);
    };
    auto ldB = [&](int kt) {
        const float* src = &Wr[(size_t)(kt * 32 + bk) * NDIM + n0 + bq];
        #pragma unroll
        for (int i = 0; i < 4; i++) br[i] = *(const float4*)(src + i * 4);
    };
    auto stage = [&](int buf) {
        float* Ad = Asb + buf * AS_FLOATS;
        float* Bd = Bsb + buf * BS_FLOATS;
        #pragma unroll
        for (int i = 0; i < 4; i++) {
            float4 v = ar[i];
            if (GATHER)
                v = make_float4(f2tf32(v.x), f2tf32(v.y), f2tf32(v.z), f2tf32(v.w));
            *(float4*)&Ad[am * 36 + ah * 16 + i * 4] = v;
            *(float4*)&Bd[bk * 132 + bq + i * 4] = br[i];
        }
    };
    auto compute = [&](int buf) {
        float* Ad = Asb + buf * AS_FLOATS;
        float* Bd = Bsb + buf * BS_FLOATS;
        #pragma unroll
        for (int kk = 0; kk < 32; kk += 8) {
            uint32_t afr[2][4];
            #pragma unroll
            for (int mi = 0; mi < 2; mi++) {
                int mr = m0w + mi * 16 + g;
                afr[mi][0] = __float_as_uint(Ad[mr * 36 + kk + tg]);
                afr[mi][1] = __float_as_uint(Ad[(mr + 8) * 36 + kk + tg]);
                afr[mi][2] = __float_as_uint(Ad[mr * 36 + kk + tg + 4]);
                afr[mi][3] = __float_as_uint(Ad[(mr + 8) * 36 + kk + tg + 4]);
            }
            uint32_t bfr[8][2];
            #pragma unroll
            for (int nf = 0; nf < 8; nf++) {
                int nc = n0w + nf * 8 + g;
                bfr[nf][0] = __float_as_uint(Bd[(kk + tg) * 132 + nc]);
                bfr[nf][1] = __float_as_uint(Bd[(kk + tg + 4) * 132 + nc]);
            }
            #pragma unroll
            for (int mi = 0; mi < 2; mi++)
                #pragma unroll
                for (int nf = 0; nf < 8; nf++)
                    mma_tf32(acc[mi][nf],
                             afr[mi][0], afr[mi][1], afr[mi][2], afr[mi][3],
                             bfr[nf][0], bfr[nf][1]);
        }
    };

    constexpr int NT = KDIM / 32;
    ldA(0); ldB(0);
    #pragma unroll 2
    for (int kt = 0; kt < NT; kt++) {
        int buf = kt & 1;
        stage(buf);
        __syncthreads();
        if (kt + 1 < NT) { ldA(kt + 1); ldB(kt + 1); }
        compute(buf);
    }

    // ---- epilogue: bias + store ----
    float* Cm = GATHER ? g_x : Cparam;
    #pragma unroll
    for (int mi = 0; mi < 2; mi++) {
        #pragma unroll
        for (int nf = 0; nf < 8; nf++) {
            int n = n0 + n0w + nf * 8 + 2 * tg;
            float bv0 = bias[n], bv1 = bias[n + 1];
            size_t mA = (size_t)(m0 + m0w + mi * 16 + g);
            size_t mB = mA + 8;
            float2 r0 = make_float2(acc[mi][nf][0] + bv0, acc[mi][nf][1] + bv1);
            float2 r1 = make_float2(acc[mi][nf][2] + bv0, acc[mi][nf][3] + bv1);
            *(float2*)&Cm[mA * NDIM + n] = r0;
            *(float2*)&Cm[mB * NDIM + n] = r1;
        }
    }
}

// ---------------- LayerNorm + exact GELU, in-place, writes tf32-rounded ----------
__global__ void k_lngelu(const float* __restrict__ gamma,
                         const float* __restrict__ beta) {
    int w = blockIdx.x * (blockDim.x >> 5) + (threadIdx.x >> 5);
    if (w >= ROWS) return;
    int lane = threadIdx.x & 31;
    float* row = g_x + (size_t)w * HID;
    float4 v[4];
    float s = 0.f, ss = 0.f;
    #pragma unroll
    for (int p = 0; p < 4; p++) {
        v[p] = *(float4*)&row[p * 128 + lane * 4];
        s  += v[p].x + v[p].y + v[p].z + v[p].w;
        ss += v[p].x * v[p].x + v[p].y * v[p].y + v[p].z * v[p].z + v[p].w * v[p].w;
    }
    #pragma unroll
    for (int o = 16; o; o >>= 1) {
        s  += __shfl_xor_sync(0xffffffffu, s, o);
        ss += __shfl_xor_sync(0xffffffffu, ss, o);
    }
    float mu = s * (1.f / HID);
    float var = ss * (1.f / HID) - mu * mu;
    float r = rsqrtf(var + 1e-5f);
    #pragma unroll
    for (int p = 0; p < 4; p++) {
        int k0 = p * 128 + lane * 4;
        float vals[4] = {v[p].x, v[p].y, v[p].z, v[p].w};
        #pragma unroll
        for (int j = 0; j < 4; j++) {
            float t = (vals[j] - mu) * r * gamma[k0 + j] + beta[k0 + j];
            vals[j] = f2tf32(t * normcdff(t));   // pre-rounded for GEMM2
        }
        *(float4*)&row[k0] = make_float4(vals[0], vals[1], vals[2], vals[3]);
    }
}

// ---------------- launch ----------------
extern "C" void kernel_launch(void* const* d_in, const int* in_sizes, int n_in,
                              void* d_out, int out_size) {
    int p = 0;
    auto pick = [&]() -> const void* {
        while (p < n_in && in_sizes[p] <= 1) p++;
        return d_in[p++];
    };
    const int*   edge  = (const int*)  pick();
    const float* poh   = (const float*)pick();
    const float* emb   = (const float*)pick();
    const float* W1    = (const float*)pick();
    const float* b1    = (const float*)pick();
    const float* gamma = (const float*)pick();
    const float* beta  = (const float*)pick();
    const float* W2    = (const float*)pick();
    const float* b2    = (const float*)pick();
    float* out = (float*)d_out;

    cudaFuncSetAttribute(k_gemm_tc<K1, HID, 1>,
                         cudaFuncAttributeMaxDynamicSharedMemorySize, GEMM_SMEM_BYTES);
    cudaFuncSetAttribute(k_gemm_tc<HID, OUTD, 0>,
                         cudaFuncAttributeMaxDynamicSharedMemorySize, GEMM_SMEM_BYTES);

    k_argmax<<<(Nn + 255) / 256, 256>>>(poh);
    k_init_emb<<<(Nn * Dd + 255) / 256, 256>>>(emb);

    k_prepW1<<<(K1 * HID + 255) / 256, 256>>>(W1);
    k_prepW2<<<(HID * OUTD + 255) / 256, 256>>>(W2);

    k_zero_deg<<<256, 256>>>();
    k_count<<<(Bq * Ee + 255) / 256, 256>>>(edge);
    k_scan<<<Bq, 640>>>();
    k_scatter<<<(Bq * Ee + 255) / 256, 256>>>(edge);

    for (int h = 0; h < HOPS; h++)
        k_spmm<<<ROWS / 8, 256>>>(h);

    float* w1r; cudaGetSymbolAddress((void**)&w1r, g_W1r);
    float* w2r; cudaGetSymbolAddress((void**)&w2r, g_W2r);

    {
        dim3 grid(HID / 128, ROWS / 128);
        k_gemm_tc<K1, HID, 1><<<grid, 256, GEMM_SMEM_BYTES>>>(w1r, b1, nullptr);
    }

    k_lngelu<<<ROWS / 8, 256>>>(gamma, beta);

    {
        dim3 grid(OUTD / 128, ROWS / 128);
        k_gemm_tc<HID, OUTD, 0><<<grid, 256, GEMM_SMEM_BYTES>>>(w2r, b2, out);
    }
}

// round 5
// speedup vs baseline: 2.2811x; 1.0760x over previous
#include <cuda_runtime.h>
#include <math.h>
#include <stdint.h>

#define Bq   8
#define Nn   20000
#define Ee   320000
#define Ccells 128
#define Dd   64
#define HOPS 4
#define HID  512
#define OUTD 256
#define K1   (HOPS*Dd)      // 256
#define ROWS (Bq*Nn)        // 160000

// ---------------- device scratch (static, no allocation) ----------------
__device__ int   g_idx[Nn];
__device__ float g_init[Nn*Dd];
__device__ float g_hops[HOPS][(size_t)Bq*Nn*Dd];
__device__ float g_x[(size_t)ROWS*HID];
__device__ int   g_deg[ROWS];
__device__ int   g_cursor[ROWS];
__device__ int   g_rowptr[Bq*(Nn+1)];
__device__ int   g_cols[(size_t)Bq*Ee];
__device__ float g_W1r[(size_t)K1*HID];    // [k_blocked][n], tf32-rounded, rows permuted
__device__ float g_W2r[(size_t)HID*OUTD];  // [k][n], tf32-rounded

// ---------------- helpers ----------------
__device__ __forceinline__ float f2tf32(float x) {
    uint32_t u;
    asm("cvt.rna.tf32.f32 %0, %1;" : "=r"(u) : "f"(x));
    return __uint_as_float(u);
}

__device__ __forceinline__ void mma_tf32(float c[4],
    uint32_t a0, uint32_t a1, uint32_t a2, uint32_t a3,
    uint32_t b0, uint32_t b1) {
    asm volatile(
        "mma.sync.aligned.m16n8k8.row.col.f32.tf32.tf32.f32 "
        "{%0,%1,%2,%3}, {%4,%5,%6,%7}, {%8,%9}, {%0,%1,%2,%3};\n"
        : "+f"(c[0]), "+f"(c[1]), "+f"(c[2]), "+f"(c[3])
        : "r"(a0), "r"(a1), "r"(a2), "r"(a3), "r"(b0), "r"(b1));
}

// ---------------- argmax over cells -> gene index ----------------
__global__ void k_argmax(const float* __restrict__ poh) {
    int n = blockIdx.x * blockDim.x + threadIdx.x;
    if (n >= Nn) return;
    float best = poh[n]; int bi = 0;
    for (int c = 1; c < Ccells; c++) {
        float v = poh[(size_t)c * Nn + n];
        if (v > best) { best = v; bi = c; }
    }
    g_idx[n] = bi;
}

__global__ void k_init_emb(const float* __restrict__ emb) {
    int i = blockIdx.x * blockDim.x + threadIdx.x;
    if (i >= Nn * Dd) return;
    int n = i >> 6, d = i & 63;
    g_init[i] = emb[g_idx[n] * Dd + d];
}

// ---------------- weight prep ----------------
// W1 (K1=256 rows interleaved k=d*4+h, HID cols) -> blocked rows kb=h*64+d, tf32
__global__ void k_prepW1(const float* __restrict__ W1) {
    int i = blockIdx.x * blockDim.x + threadIdx.x;
    if (i >= K1 * HID) return;
    int k = i / HID, n = i - k * HID;
    int d = k >> 2, h = k & 3;
    g_W1r[(size_t)(h * 64 + d) * HID + n] = f2tf32(W1[i]);
}
__global__ void k_prepW2(const float* __restrict__ W2) {
    int i = blockIdx.x * blockDim.x + threadIdx.x;
    if (i >= HID * OUTD) return;
    g_W2r[i] = f2tf32(W2[i]);
}

// ---------------- CSR build ----------------
__global__ void k_zero_deg() {
    for (int i = blockIdx.x * blockDim.x + threadIdx.x; i < ROWS;
         i += gridDim.x * blockDim.x)
        g_deg[i] = 0;
}

__global__ void k_count(const int* __restrict__ edge) {
    int e = blockIdx.x * blockDim.x + threadIdx.x;
    if (e >= Bq * Ee) return;
    int b = e / Ee, i = e - b * Ee;
    int row = edge[(size_t)b * 2 * Ee + i];
    atomicAdd(&g_deg[b * Nn + row], 1);
}

__global__ void k_scan() {
    __shared__ int part[640];
    int b = blockIdx.x;
    int t = threadIdx.x;
    int base = b * Nn;
    int s = 0;
    for (int i = 0; i < 32; i++) {
        int r = t * 32 + i;
        if (r < Nn) s += g_deg[base + r];
    }
    part[t] = s;
    __syncthreads();
    if (t == 0) {
        int run = 0;
        for (int i = 0; i < 640; i++) { int x = part[i]; part[i] = run; run += x; }
        g_rowptr[b * (Nn + 1) + Nn] = run;
    }
    __syncthreads();
    int off = part[t];
    for (int i = 0; i < 32; i++) {
        int r = t * 32 + i;
        if (r < Nn) {
            g_rowptr[b * (Nn + 1) + r] = off;
            g_cursor[base + r] = off;
            off += g_deg[base + r];
        }
    }
}

__global__ void k_scatter(const int* __restrict__ edge) {
    int e = blockIdx.x * blockDim.x + threadIdx.x;
    if (e >= Bq * Ee) return;
    int b = e / Ee, i = e - b * Ee;
    int row = edge[(size_t)b * 2 * Ee + i];
    int col = edge[(size_t)b * 2 * Ee + Ee + i];
    int pos = atomicAdd(&g_cursor[b * Nn + row], 1);
    g_cols[(size_t)b * Ee + pos] = col;
}

// -------- SPMM gather: half-warp (16 lanes x float4) per edge, 2 edges/iter ----
__global__ void k_spmm(int hop) {
    int w = blockIdx.x * (blockDim.x >> 5) + (threadIdx.x >> 5);
    if (w >= ROWS) return;
    int lane = threadIdx.x & 31;
    int hw   = lane >> 4;        // half-warp id
    int l4   = lane & 15;        // float4 slot within 64-float row
    int b = w / Nn, n = w - b * Nn;
    int s = g_rowptr[b * (Nn + 1) + n];
    int e = g_rowptr[b * (Nn + 1) + n + 1];
    const float4* __restrict__ src =
        (hop == 0) ? (const float4*)g_init : (const float4*)g_hops[hop - 1];
    size_t grow = (hop == 0) ? 0 : (size_t)b * Nn;
    const int* __restrict__ cols = &g_cols[(size_t)b * Ee];

    float4 a0 = make_float4(0.f, 0.f, 0.f, 0.f), a1 = a0;
    int j = s + hw;
    // unroll 2: each half-warp keeps 2 gathers in flight (4 edges per warp)
    for (; j + 2 < e; j += 4) {
        int c0 = cols[j], c1 = cols[j + 2];
        float4 v0 = src[(grow + (size_t)c0) * 16 + l4];
        float4 v1 = src[(grow + (size_t)c1) * 16 + l4];
        a0.x += v0.x; a0.y += v0.y; a0.z += v0.z; a0.w += v0.w;
        a1.x += v1.x; a1.y += v1.y; a1.z += v1.z; a1.w += v1.w;
    }
    if (j < e) {
        float4 v = src[(grow + (size_t)cols[j]) * 16 + l4];
        a0.x += v.x; a0.y += v.y; a0.z += v.z; a0.w += v.w;
    }
    a0.x += a1.x; a0.y += a1.y; a0.z += a1.z; a0.w += a1.w;
    // combine the two half-warps
    a0.x += __shfl_xor_sync(0xffffffffu, a0.x, 16);
    a0.y += __shfl_xor_sync(0xffffffffu, a0.y, 16);
    a0.z += __shfl_xor_sync(0xffffffffu, a0.z, 16);
    a0.w += __shfl_xor_sync(0xffffffffu, a0.w, 16);
    if (hw == 0)
        ((float4*)g_hops[hop])[(size_t)w * 16 + l4] = a0;
}

// ---------------- TF32 tensor-core GEMM: 128x128 CTA, K-step 16 ----------------
// 2 CTAs/SM (36.5KB smem, <=128 regs). Register-staged double-buffer pipeline.
// GATHER=1: A from g_hops (blocked k = h*64+d), C -> g_x, bias=b1, cvt at stage.
// GATHER=0: A = g_x (pre-rounded tf32 by LN), C -> Cparam, bias=b2.
#define AS_FLOATS (128*20)
#define BS_FLOATS (16*132)
#define GEMM_SMEM_BYTES ((2*AS_FLOATS + 2*BS_FLOATS)*4)

template <int KDIM, int NDIM, int GATHER>
__global__ void __launch_bounds__(256, 2)
k_gemm_tc(const float* __restrict__ Wr,
          const float* __restrict__ bias,
          float* __restrict__ Cparam) {
    extern __shared__ float sm[];
    float* Asb = sm;                    // 2 buffers of [128][20]
    float* Bsb = sm + 2 * AS_FLOATS;    // 2 buffers of [16][132]

    const int tid  = threadIdx.x;
    const int lane = tid & 31;
    const int warp = tid >> 5;
    const int g    = lane >> 2;
    const int tg   = lane & 3;
    const int wm   = warp & 3;
    const int wn   = warp >> 2;
    const int m0w  = wm * 32;
    const int n0w  = wn * 64;

    const int n0 = blockIdx.x * 128;
    const int m0 = blockIdx.y * 128;

    float acc[2][8][4];
    #pragma unroll
    for (int i = 0; i < 2; i++)
        #pragma unroll
        for (int j = 0; j < 8; j++)
            #pragma unroll
            for (int q = 0; q < 4; q++) acc[i][j][q] = 0.f;

    const int am = tid >> 1;         // A row 0..127
    const int ah = (tid & 1) * 8;    // k offset (8 cols per thread)
    const int bk = tid >> 4;         // B k row 0..15
    const int bq = (tid & 15) * 8;   // B n offset

    float4 ar[2], br[2];

    auto ldA = [&](int kt) {
        const int k0 = kt * 16;
        const float* src;
        if (GATHER) {
            int h  = k0 >> 6;
            int d0 = (k0 & 63) + ah;
            src = &g_hops[h][(size_t)(m0 + am) * Dd + d0];
        } else {
            src = &g_x[(size_t)(m0 + am) * KDIM + k0 + ah];
        }
        ar[0] = *(const float4*)(src);
        ar[1] = *(const float4*)(src + 4);
    };
    auto ldB = [&](int kt) {
        const float* src = &Wr[(size_t)(kt * 16 + bk) * NDIM + n0 + bq];
        br[0] = *(const float4*)(src);
        br[1] = *(const float4*)(src + 4);
    };
    auto stage = [&](int buf) {
        float* Ad = Asb + buf * AS_FLOATS;
        float* Bd = Bsb + buf * BS_FLOATS;
        #pragma unroll
        for (int i = 0; i < 2; i++) {
            float4 v = ar[i];
            if (GATHER)
                v = make_float4(f2tf32(v.x), f2tf32(v.y), f2tf32(v.z), f2tf32(v.w));
            *(float4*)&Ad[am * 20 + ah + i * 4] = v;
            *(float4*)&Bd[bk * 132 + bq + i * 4] = br[i];
        }
    };
    auto compute = [&](int buf) {
        float* Ad = Asb + buf * AS_FLOATS;
        float* Bd = Bsb + buf * BS_FLOATS;
        #pragma unroll
        for (int kk = 0; kk < 16; kk += 8) {
            uint32_t afr[2][4];
            #pragma unroll
            for (int mi = 0; mi < 2; mi++) {
                int mr = m0w + mi * 16 + g;
                afr[mi][0] = __float_as_uint(Ad[mr * 20 + kk + tg]);
                afr[mi][1] = __float_as_uint(Ad[(mr + 8) * 20 + kk + tg]);
                afr[mi][2] = __float_as_uint(Ad[mr * 20 + kk + tg + 4]);
                afr[mi][3] = __float_as_uint(Ad[(mr + 8) * 20 + kk + tg + 4]);
            }
            uint32_t bfr[8][2];
            #pragma unroll
            for (int nf = 0; nf < 8; nf++) {
                int nc = n0w + nf * 8 + g;
                bfr[nf][0] = __float_as_uint(Bd[(kk + tg) * 132 + nc]);
                bfr[nf][1] = __float_as_uint(Bd[(kk + tg + 4) * 132 + nc]);
            }
            #pragma unroll
            for (int mi = 0; mi < 2; mi++)
                #pragma unroll
                for (int nf = 0; nf < 8; nf++)
                    mma_tf32(acc[mi][nf],
                             afr[mi][0], afr[mi][1], afr[mi][2], afr[mi][3],
                             bfr[nf][0], bfr[nf][1]);
        }
    };

    constexpr int NT = KDIM / 16;
    ldA(0); ldB(0);
    #pragma unroll 2
    for (int kt = 0; kt < NT; kt++) {
        int buf = kt & 1;
        stage(buf);
        __syncthreads();
        if (kt + 1 < NT) { ldA(kt + 1); ldB(kt + 1); }
        compute(buf);
    }

    // ---- epilogue: bias + store ----
    float* Cm = GATHER ? g_x : Cparam;
    #pragma unroll
    for (int mi = 0; mi < 2; mi++) {
        #pragma unroll
        for (int nf = 0; nf < 8; nf++) {
            int n = n0 + n0w + nf * 8 + 2 * tg;
            float bv0 = bias[n], bv1 = bias[n + 1];
            size_t mA = (size_t)(m0 + m0w + mi * 16 + g);
            size_t mB = mA + 8;
            float2 r0 = make_float2(acc[mi][nf][0] + bv0, acc[mi][nf][1] + bv1);
            float2 r1 = make_float2(acc[mi][nf][2] + bv0, acc[mi][nf][3] + bv1);
            *(float2*)&Cm[mA * NDIM + n] = r0;
            *(float2*)&Cm[mB * NDIM + n] = r1;
        }
    }
}

// ---------------- LayerNorm + exact GELU, in-place, writes tf32-rounded ----------
__global__ void k_lngelu(const float* __restrict__ gamma,
                         const float* __restrict__ beta) {
    int w = blockIdx.x * (blockDim.x >> 5) + (threadIdx.x >> 5);
    if (w >= ROWS) return;
    int lane = threadIdx.x & 31;
    float* row = g_x + (size_t)w * HID;
    float4 v[4];
    float s = 0.f, ss = 0.f;
    #pragma unroll
    for (int p = 0; p < 4; p++) {
        v[p] = *(float4*)&row[p * 128 + lane * 4];
        s  += v[p].x + v[p].y + v[p].z + v[p].w;
        ss += v[p].x * v[p].x + v[p].y * v[p].y + v[p].z * v[p].z + v[p].w * v[p].w;
    }
    #pragma unroll
    for (int o = 16; o; o >>= 1) {
        s  += __shfl_xor_sync(0xffffffffu, s, o);
        ss += __shfl_xor_sync(0xffffffffu, ss, o);
    }
    float mu = s * (1.f / HID);
    float var = ss * (1.f / HID) - mu * mu;
    float r = rsqrtf(var + 1e-5f);
    #pragma unroll
    for (int p = 0; p < 4; p++) {
        int k0 = p * 128 + lane * 4;
        float vals[4] = {v[p].x, v[p].y, v[p].z, v[p].w};
        #pragma unroll
        for (int j = 0; j < 4; j++) {
            float t = (vals[j] - mu) * r * gamma[k0 + j] + beta[k0 + j];
            vals[j] = f2tf32(t * normcdff(t));   // pre-rounded for GEMM2
        }
        *(float4*)&row[k0] = make_float4(vals[0], vals[1], vals[2], vals[3]);
    }
}

// ---------------- launch ----------------
extern "C" void kernel_launch(void* const* d_in, const int* in_sizes, int n_in,
                              void* d_out, int out_size) {
    int p = 0;
    auto pick = [&]() -> const void* {
        while (p < n_in && in_sizes[p] <= 1) p++;
        return d_in[p++];
    };
    const int*   edge  = (const int*)  pick();
    const float* poh   = (const float*)pick();
    const float* emb   = (const float*)pick();
    const float* W1    = (const float*)pick();
    const float* b1    = (const float*)pick();
    const float* gamma = (const float*)pick();
    const float* beta  = (const float*)pick();
    const float* W2    = (const float*)pick();
    const float* b2    = (const float*)pick();
    float* out = (float*)d_out;

    cudaFuncSetAttribute(k_gemm_tc<K1, HID, 1>,
                         cudaFuncAttributeMaxDynamicSharedMemorySize, GEMM_SMEM_BYTES);
    cudaFuncSetAttribute(k_gemm_tc<HID, OUTD, 0>,
                         cudaFuncAttributeMaxDynamicSharedMemorySize, GEMM_SMEM_BYTES);

    k_argmax<<<(Nn + 255) / 256, 256>>>(poh);
    k_init_emb<<<(Nn * Dd + 255) / 256, 256>>>(emb);

    k_prepW1<<<(K1 * HID + 255) / 256, 256>>>(W1);
    k_prepW2<<<(HID * OUTD + 255) / 256, 256>>>(W2);

    k_zero_deg<<<256, 256>>>();
    k_count<<<(Bq * Ee + 255) / 256, 256>>>(edge);
    k_scan<<<Bq, 640>>>();
    k_scatter<<<(Bq * Ee + 255) / 256, 256>>>(edge);

    for (int h = 0; h < HOPS; h++)
        k_spmm<<<ROWS / 8, 256>>>(h);

    float* w1r; cudaGetSymbolAddress((void**)&w1r, g_W1r);
    float* w2r; cudaGetSymbolAddress((void**)&w2r, g_W2r);

    {
        dim3 grid(HID / 128, ROWS / 128);
        k_gemm_tc<K1, HID, 1><<<grid, 256, GEMM_SMEM_BYTES>>>(w1r, b1, nullptr);
    }

    k_lngelu<<<ROWS / 8, 256>>>(gamma, beta);

    {
        dim3 grid(OUTD / 128, ROWS / 128);
        k_gemm_tc<HID, OUTD, 0><<<grid, 256, GEMM_SMEM_BYTES>>>(w2r, b2, out);
    }
}

// round 6
// speedup vs baseline: 2.4646x; 1.0805x over previous
#include <cuda_runtime.h>
#include <math.h>
#include <stdint.h>

#define Bq   8
#define Nn   20000
#define Ee   320000
#define Ccells 128
#define Dd   64
#define HOPS 4
#define HID  512
#define OUTD 256
#define K1   (HOPS*Dd)      // 256
#define ROWS (Bq*Nn)        // 160000

// ---------------- device scratch (static, no allocation) ----------------
__device__ int   g_idx[Nn];
__device__ float g_init[Nn*Dd];
__device__ float g_hops[HOPS][(size_t)Bq*Nn*Dd];
__device__ float g_x[(size_t)ROWS*HID];
__device__ int   g_deg[ROWS];
__device__ int   g_cursor[ROWS];
__device__ int   g_rowptr[Bq*(Nn+1)];
__device__ int   g_cols[(size_t)Bq*Ee];
__device__ float g_W1r[(size_t)K1*HID];    // [k_blocked][n], tf32-rounded, rows permuted
__device__ float g_W2r[(size_t)HID*OUTD];  // [k][n], tf32-rounded

// ---------------- helpers ----------------
__device__ __forceinline__ float f2tf32(float x) {
    uint32_t u;
    asm("cvt.rna.tf32.f32 %0, %1;" : "=r"(u) : "f"(x));
    return __uint_as_float(u);
}

__device__ __forceinline__ void mma_tf32(float c[4],
    uint32_t a0, uint32_t a1, uint32_t a2, uint32_t a3,
    uint32_t b0, uint32_t b1) {
    asm volatile(
        "mma.sync.aligned.m16n8k8.row.col.f32.tf32.tf32.f32 "
        "{%0,%1,%2,%3}, {%4,%5,%6,%7}, {%8,%9}, {%0,%1,%2,%3};\n"
        : "+f"(c[0]), "+f"(c[1]), "+f"(c[2]), "+f"(c[3])
        : "r"(a0), "r"(a1), "r"(a2), "r"(a3), "r"(b0), "r"(b1));
}

__device__ __forceinline__ void cp16(uint32_t smem_addr, const void* gptr) {
    asm volatile("cp.async.cg.shared.global [%0], [%1], 16;"
                 :: "r"(smem_addr), "l"(gptr) : "memory");
}
__device__ __forceinline__ void cp_commit() {
    asm volatile("cp.async.commit_group;" ::: "memory");
}
template <int N> __device__ __forceinline__ void cp_wait() {
    asm volatile("cp.async.wait_group %0;" :: "n"(N) : "memory");
}
__device__ __forceinline__ uint32_t smem_u32(const void* p) {
    uint32_t a;
    asm("{ .reg .u64 t; cvta.to.shared.u64 t, %1; cvt.u32.u64 %0, t; }" : "=r"(a) : "l"(p));
    return a;
}

// ---------------- argmax over cells -> gene index ----------------
__global__ void k_argmax(const float* __restrict__ poh) {
    int n = blockIdx.x * blockDim.x + threadIdx.x;
    if (n >= Nn) return;
    float best = poh[n]; int bi = 0;
    for (int c = 1; c < Ccells; c++) {
        float v = poh[(size_t)c * Nn + n];
        if (v > best) { best = v; bi = c; }
    }
    g_idx[n] = bi;
}

__global__ void k_init_emb(const float* __restrict__ emb) {
    int i = blockIdx.x * blockDim.x + threadIdx.x;
    if (i >= Nn * Dd) return;
    int n = i >> 6, d = i & 63;
    g_init[i] = emb[g_idx[n] * Dd + d];
}

// ---------------- weight prep ----------------
__global__ void k_prepW1(const float* __restrict__ W1) {
    int i = blockIdx.x * blockDim.x + threadIdx.x;
    if (i >= K1 * HID) return;
    int k = i / HID, n = i - k * HID;
    int d = k >> 2, h = k & 3;
    g_W1r[(size_t)(h * 64 + d) * HID + n] = f2tf32(W1[i]);
}
__global__ void k_prepW2(const float* __restrict__ W2) {
    int i = blockIdx.x * blockDim.x + threadIdx.x;
    if (i >= HID * OUTD) return;
    g_W2r[i] = f2tf32(W2[i]);
}

// ---------------- CSR build ----------------
__global__ void k_zero_deg() {
    for (int i = blockIdx.x * blockDim.x + threadIdx.x; i < ROWS;
         i += gridDim.x * blockDim.x)
        g_deg[i] = 0;
}

__global__ void k_count(const int* __restrict__ edge) {
    int e = blockIdx.x * blockDim.x + threadIdx.x;
    if (e >= Bq * Ee) return;
    int b = e / Ee, i = e - b * Ee;
    int row = edge[(size_t)b * 2 * Ee + i];
    atomicAdd(&g_deg[b * Nn + row], 1);
}

__global__ void k_scan() {
    __shared__ int part[640];
    int b = blockIdx.x;
    int t = threadIdx.x;
    int base = b * Nn;
    int s = 0;
    for (int i = 0; i < 32; i++) {
        int r = t * 32 + i;
        if (r < Nn) s += g_deg[base + r];
    }
    part[t] = s;
    __syncthreads();
    if (t == 0) {
        int run = 0;
        for (int i = 0; i < 640; i++) { int x = part[i]; part[i] = run; run += x; }
        g_rowptr[b * (Nn + 1) + Nn] = run;
    }
    __syncthreads();
    int off = part[t];
    for (int i = 0; i < 32; i++) {
        int r = t * 32 + i;
        if (r < Nn) {
            g_rowptr[b * (Nn + 1) + r] = off;
            g_cursor[base + r] = off;
            off += g_deg[base + r];
        }
    }
}

__global__ void k_scatter(const int* __restrict__ edge) {
    int e = blockIdx.x * blockDim.x + threadIdx.x;
    if (e >= Bq * Ee) return;
    int b = e / Ee, i = e - b * Ee;
    int row = edge[(size_t)b * 2 * Ee + i];
    int col = edge[(size_t)b * 2 * Ee + Ee + i];
    int pos = atomicAdd(&g_cursor[b * Nn + row], 1);
    g_cols[(size_t)b * Ee + pos] = col;
}

// -------- SPMM gather: half-warp (16 lanes x float4) per edge, 2 edges/iter ----
// Output written tf32-rounded (feeds GEMM1 A raw, and next hop).
__global__ void k_spmm(int hop) {
    int w = blockIdx.x * (blockDim.x >> 5) + (threadIdx.x >> 5);
    if (w >= ROWS) return;
    int lane = threadIdx.x & 31;
    int hw   = lane >> 4;
    int l4   = lane & 15;
    int b = w / Nn, n = w - b * Nn;
    int s = g_rowptr[b * (Nn + 1) + n];
    int e = g_rowptr[b * (Nn + 1) + n + 1];
    const float4* __restrict__ src =
        (hop == 0) ? (const float4*)g_init : (const float4*)g_hops[hop - 1];
    size_t grow = (hop == 0) ? 0 : (size_t)b * Nn;
    const int* __restrict__ cols = &g_cols[(size_t)b * Ee];

    float4 a0 = make_float4(0.f, 0.f, 0.f, 0.f), a1 = a0;
    int j = s + hw;
    for (; j + 2 < e; j += 4) {
        int c0 = cols[j], c1 = cols[j + 2];
        float4 v0 = src[(grow + (size_t)c0) * 16 + l4];
        float4 v1 = src[(grow + (size_t)c1) * 16 + l4];
        a0.x += v0.x; a0.y += v0.y; a0.z += v0.z; a0.w += v0.w;
        a1.x += v1.x; a1.y += v1.y; a1.z += v1.z; a1.w += v1.w;
    }
    if (j < e) {
        float4 v = src[(grow + (size_t)cols[j]) * 16 + l4];
        a0.x += v.x; a0.y += v.y; a0.z += v.z; a0.w += v.w;
    }
    a0.x += a1.x; a0.y += a1.y; a0.z += a1.z; a0.w += a1.w;
    a0.x += __shfl_xor_sync(0xffffffffu, a0.x, 16);
    a0.y += __shfl_xor_sync(0xffffffffu, a0.y, 16);
    a0.z += __shfl_xor_sync(0xffffffffu, a0.z, 16);
    a0.w += __shfl_xor_sync(0xffffffffu, a0.w, 16);
    if (hw == 0) {
        float4 o = make_float4(f2tf32(a0.x), f2tf32(a0.y), f2tf32(a0.z), f2tf32(a0.w));
        ((float4*)g_hops[hop])[(size_t)w * 16 + l4] = o;
    }
}

// ---------------- TF32 tensor-core GEMM: 128x128 CTA, K-step 16 ----------------
// 3-stage cp.async pipeline, 2 CTAs/SM. All operands pre-rounded to tf32.
// GATHER=1: A from g_hops (blocked k = h*64+d), C -> g_x, bias=b1
// GATHER=0: A = g_x, C -> Cparam, bias=b2
#define AS_FLOATS (128*20)
#define BS_FLOATS (16*132)
#define NSTAGE 3
#define GEMM_SMEM_BYTES (NSTAGE*(AS_FLOATS + BS_FLOATS)*4)

template <int KDIM, int NDIM, int GATHER>
__global__ void __launch_bounds__(256, 2)
k_gemm_tc(const float* __restrict__ Wr,
          const float* __restrict__ bias,
          float* __restrict__ Cparam) {
    extern __shared__ float sm[];
    float* Asb = sm;                          // NSTAGE buffers [128][20]
    float* Bsb = sm + NSTAGE * AS_FLOATS;     // NSTAGE buffers [16][132]

    const int tid  = threadIdx.x;
    const int lane = tid & 31;
    const int warp = tid >> 5;
    const int g    = lane >> 2;
    const int tg   = lane & 3;
    const int wm   = warp & 3;
    const int wn   = warp >> 2;
    const int m0w  = wm * 32;
    const int n0w  = wn * 64;

    const int n0 = blockIdx.x * 128;
    const int m0 = blockIdx.y * 128;

    float acc[2][8][4];
    #pragma unroll
    for (int i = 0; i < 2; i++)
        #pragma unroll
        for (int j = 0; j < 8; j++)
            #pragma unroll
            for (int q = 0; q < 4; q++) acc[i][j][q] = 0.f;

    const int am = tid >> 1;         // A row 0..127
    const int ah = (tid & 1) * 8;    // k offset (8 cols per thread)
    const int bk = tid >> 4;         // B k row 0..15
    const int bq = (tid & 15) * 8;   // B n offset

    const uint32_t a_sm_base = smem_u32(&Asb[am * 20 + ah]);
    const uint32_t b_sm_base = smem_u32(&Bsb[bk * 132 + bq]);

    auto issue = [&](int kt) {
        const int buf = kt % NSTAGE;
        const int k0 = kt * 16;
        const float* srcA;
        if (GATHER) {
            srcA = &g_hops[k0 >> 6][(size_t)(m0 + am) * Dd + (k0 & 63) + ah];
        } else {
            srcA = &g_x[(size_t)(m0 + am) * KDIM + k0 + ah];
        }
        uint32_t a_sm = a_sm_base + buf * (AS_FLOATS * 4);
        cp16(a_sm, srcA);
        cp16(a_sm + 16, srcA + 4);
        const float* srcB = &Wr[(size_t)(k0 + bk) * NDIM + n0 + bq];
        uint32_t b_sm = b_sm_base + buf * (BS_FLOATS * 4);
        cp16(b_sm, srcB);
        cp16(b_sm + 16, srcB + 4);
        cp_commit();
    };

    auto compute = [&](int buf) {
        float* Ad = Asb + buf * AS_FLOATS;
        float* Bd = Bsb + buf * BS_FLOATS;
        #pragma unroll
        for (int kk = 0; kk < 16; kk += 8) {
            uint32_t afr[2][4];
            #pragma unroll
            for (int mi = 0; mi < 2; mi++) {
                int mr = m0w + mi * 16 + g;
                afr[mi][0] = __float_as_uint(Ad[mr * 20 + kk + tg]);
                afr[mi][1] = __float_as_uint(Ad[(mr + 8) * 20 + kk + tg]);
                afr[mi][2] = __float_as_uint(Ad[mr * 20 + kk + tg + 4]);
                afr[mi][3] = __float_as_uint(Ad[(mr + 8) * 20 + kk + tg + 4]);
            }
            uint32_t bfr[8][2];
            #pragma unroll
            for (int nf = 0; nf < 8; nf++) {
                int nc = n0w + nf * 8 + g;
                bfr[nf][0] = __float_as_uint(Bd[(kk + tg) * 132 + nc]);
                bfr[nf][1] = __float_as_uint(Bd[(kk + tg + 4) * 132 + nc]);
            }
            #pragma unroll
            for (int mi = 0; mi < 2; mi++)
                #pragma unroll
                for (int nf = 0; nf < 8; nf++)
                    mma_tf32(acc[mi][nf],
                             afr[mi][0], afr[mi][1], afr[mi][2], afr[mi][3],
                             bfr[nf][0], bfr[nf][1]);
        }
    };

    constexpr int NT = KDIM / 16;
    issue(0);
    issue(1);
    for (int kt = 0; kt < NT; kt++) {
        if (kt < NT - 1) cp_wait<1>(); else cp_wait<0>();
        __syncthreads();
        if (kt + 2 < NT) issue(kt + 2);
        compute(kt % NSTAGE);
    }

    // ---- epilogue: bias + store ----
    float* Cm = GATHER ? g_x : Cparam;
    #pragma unroll
    for (int mi = 0; mi < 2; mi++) {
        #pragma unroll
        for (int nf = 0; nf < 8; nf++) {
            int n = n0 + n0w + nf * 8 + 2 * tg;
            float bv0 = bias[n], bv1 = bias[n + 1];
            size_t mA = (size_t)(m0 + m0w + mi * 16 + g);
            size_t mB = mA + 8;
            float2 r0 = make_float2(acc[mi][nf][0] + bv0, acc[mi][nf][1] + bv1);
            float2 r1 = make_float2(acc[mi][nf][2] + bv0, acc[mi][nf][3] + bv1);
            *(float2*)&Cm[mA * NDIM + n] = r0;
            *(float2*)&Cm[mB * NDIM + n] = r1;
        }
    }
}

// ---------------- LayerNorm + exact GELU, in-place, writes tf32-rounded ----------
__global__ void k_lngelu(const float* __restrict__ gamma,
                         const float* __restrict__ beta) {
    int w = blockIdx.x * (blockDim.x >> 5) + (threadIdx.x >> 5);
    if (w >= ROWS) return;
    int lane = threadIdx.x & 31;
    float* row = g_x + (size_t)w * HID;
    float4 v[4];
    float s = 0.f, ss = 0.f;
    #pragma unroll
    for (int p = 0; p < 4; p++) {
        v[p] = *(float4*)&row[p * 128 + lane * 4];
        s  += v[p].x + v[p].y + v[p].z + v[p].w;
        ss += v[p].x * v[p].x + v[p].y * v[p].y + v[p].z * v[p].z + v[p].w * v[p].w;
    }
    #pragma unroll
    for (int o = 16; o; o >>= 1) {
        s  += __shfl_xor_sync(0xffffffffu, s, o);
        ss += __shfl_xor_sync(0xffffffffu, ss, o);
    }
    float mu = s * (1.f / HID);
    float var = ss * (1.f / HID) - mu * mu;
    float r = rsqrtf(var + 1e-5f);
    #pragma unroll
    for (int p = 0; p < 4; p++) {
        int k0 = p * 128 + lane * 4;
        float vals[4] = {v[p].x, v[p].y, v[p].z, v[p].w};
        #pragma unroll
        for (int j = 0; j < 4; j++) {
            float t = (vals[j] - mu) * r * gamma[k0 + j] + beta[k0 + j];
            vals[j] = f2tf32(t * normcdff(t));   // pre-rounded for GEMM2
        }
        *(float4*)&row[k0] = make_float4(vals[0], vals[1], vals[2], vals[3]);
    }
}

// ---------------- launch ----------------
extern "C" void kernel_launch(void* const* d_in, const int* in_sizes, int n_in,
                              void* d_out, int out_size) {
    int p = 0;
    auto pick = [&]() -> const void* {
        while (p < n_in && in_sizes[p] <= 1) p++;
        return d_in[p++];
    };
    const int*   edge  = (const int*)  pick();
    const float* poh   = (const float*)pick();
    const float* emb   = (const float*)pick();
    const float* W1    = (const float*)pick();
    const float* b1    = (const float*)pick();
    const float* gamma = (const float*)pick();
    const float* beta  = (const float*)pick();
    const float* W2    = (const float*)pick();
    const float* b2    = (const float*)pick();
    float* out = (float*)d_out;

    cudaFuncSetAttribute(k_gemm_tc<K1, HID, 1>,
                         cudaFuncAttributeMaxDynamicSharedMemorySize, GEMM_SMEM_BYTES);
    cudaFuncSetAttribute(k_gemm_tc<HID, OUTD, 0>,
                         cudaFuncAttributeMaxDynamicSharedMemorySize, GEMM_SMEM_BYTES);

    k_argmax<<<(Nn + 255) / 256, 256>>>(poh);
    k_init_emb<<<(Nn * Dd + 255) / 256, 256>>>(emb);

    k_prepW1<<<(K1 * HID + 255) / 256, 256>>>(W1);
    k_prepW2<<<(HID * OUTD + 255) / 256, 256>>>(W2);

    k_zero_deg<<<256, 256>>>();
    k_count<<<(Bq * Ee + 255) / 256, 256>>>(edge);
    k_scan<<<Bq, 640>>>();
    k_scatter<<<(Bq * Ee + 255) / 256, 256>>>(edge);

    for (int h = 0; h < HOPS; h++)
        k_spmm<<<ROWS / 8, 256>>>(h);

    float* w1r; cudaGetSymbolAddress((void**)&w1r, g_W1r);
    float* w2r; cudaGetSymbolAddress((void**)&w2r, g_W2r);

    {
        dim3 grid(HID / 128, ROWS / 128);
        k_gemm_tc<K1, HID, 1><<<grid, 256, GEMM_SMEM_BYTES>>>(w1r, b1, nullptr);
    }

    k_lngelu<<<ROWS / 8, 256>>>(gamma, beta);

    {
        dim3 grid(OUTD / 128, ROWS / 128);
        k_gemm_tc<HID, OUTD, 0><<<grid, 256, GEMM_SMEM_BYTES>>>(w2r, b2, out);
    }
}